// round 3
// baseline (speedup 1.0000x reference)
#include <cuda_runtime.h>
#include <cuda_fp16.h>
#include <cstdint>
#include <cstddef>

// Problem: B=4096, P=10, LD=TD=512, DIN=2048, BP=40960
// out = [logits 4096x10][best_lane 4096x512][best_nghl 4096x512][best_ngh 4096x512]
// NOTE: toolchain compiles via compute_103 PTX -> NO sm_103a-only features
// (no tcgen05/TMEM). Use mma.sync.m16n8k16 + cp.async (compute_80 features).

__device__ __align__(16) __half g_W1t[512 * 2048];        // W1^T fp16 [n][k]
__device__ __align__(16) __half g_ctxh[40960u * 2048];    // concat ctx fp16 [row][k]
__device__ __align__(16) __half g_embh[40960u * 512];     // relu(ctx@W1+b1) fp16

#define SW128(o) ((o) ^ (((o) >> 3) & 0x70))

__device__ __forceinline__ uint32_t smem_u32(const void* p) {
    uint32_t a;
    asm("{ .reg .u64 t; cvta.to.shared.u64 t, %1; cvt.u32.u64 %0, t; }" : "=r"(a) : "l"(p));
    return a;
}
__device__ __forceinline__ uint32_t pack_h2(float a, float b) {
    __half2 h = __floats2half2_rn(a, b);
    return *reinterpret_cast<uint32_t*>(&h);
}

#define CP16(dst, src) \
    asm volatile("cp.async.cg.shared.global [%0], [%1], 16;" :: "r"(dst), "l"(src) : "memory")
#define CP_COMMIT() asm volatile("cp.async.commit_group;" ::: "memory")
#define CP_WAIT2()  asm volatile("cp.async.wait_group 2;" ::: "memory")
#define CP_WAIT0()  asm volatile("cp.async.wait_group 0;" ::: "memory")

#define LDSM_X4(r, addr)                                                          \
    asm volatile("ldmatrix.sync.aligned.m8n8.x4.shared.b16 {%0,%1,%2,%3}, [%4];"  \
        : "=r"((r)[0]), "=r"((r)[1]), "=r"((r)[2]), "=r"((r)[3]) : "r"(addr))

#define MMA16816(d, a, b0, b1)                                                    \
    asm volatile("mma.sync.aligned.m16n8k16.row.col.f32.f16.f16.f32 "             \
        "{%0,%1,%2,%3}, {%4,%5,%6,%7}, {%8,%9}, {%0,%1,%2,%3};"                    \
        : "+f"((d)[0]), "+f"((d)[1]), "+f"((d)[2]), "+f"((d)[3])                   \
        : "r"((a)[0]), "r"((a)[1]), "r"((a)[2]), "r"((a)[3]), "r"(b0), "r"(b1))

// ---------------- Kernel 1: W1[2048,512] f32 -> W1t[512][2048] f16 ----------------
__global__ void w1t_kernel(const float* __restrict__ W1) {
    __shared__ float t[32][33];
    int kk = blockIdx.x * 32, nn = blockIdx.y * 32;
    int tx = threadIdx.x, ty = threadIdx.y;  // 32 x 8
#pragma unroll
    for (int q = 0; q < 4; q++)
        t[ty + 8 * q][tx] = W1[(size_t)(kk + ty + 8 * q) * 512 + nn + tx];
    __syncthreads();
#pragma unroll
    for (int q = 0; q < 4; q++)
        g_W1t[(size_t)(nn + ty + 8 * q) * 2048 + kk + tx] = __float2half(t[tx][ty + 8 * q]);
}

// ---------------- Kernel 2: fused concat + f32->f16: g_ctxh[row][2048] ----------------
__global__ void __launch_bounds__(256) ctx_prep_kernel(
    const float* __restrict__ agent, const float* __restrict__ lane,
    const float* __restrict__ nghl,  const float* __restrict__ ngh)
{
    int row = blockIdx.x;
    int t = threadIdx.x;
    int b = row / 10;
    int seg = t >> 6;
    int off = (t & 63) * 8;
    const float* src;
    if (seg == 0)      src = agent + (size_t)b * 512 + off;
    else if (seg == 1) src = lane + (size_t)row * 512 + off;
    else if (seg == 2) src = nghl + (size_t)row * 512 + off;
    else               src = ngh  + (size_t)row * 512 + off;
    float4 v0 = __ldg((const float4*)src);
    float4 v1 = __ldg((const float4*)src + 1);
    uint4 o;
    o.x = pack_h2(v0.x, v0.y); o.y = pack_h2(v0.z, v0.w);
    o.z = pack_h2(v1.x, v1.y); o.w = pack_h2(v1.z, v1.w);
    *(uint4*)(g_ctxh + (size_t)row * 2048 + t * 8) = o;
}

// ---------------- Kernel 3: GEMM1 emb = relu(ctx @ W1 + b1) via mma.sync ----------------
// CTA tile 128x128, 8 warps (4m x 2n), warp tile 32x64, K-chunk 64, 4-stage cp.async.
#define STAGES   4
#define STAGE_SZ 16384                      // 128 rows x 128 bytes
#define G1_SMEM  (STAGES * STAGE_SZ * 2)    // 131072

__global__ void __launch_bounds__(256, 1) gemm1_kernel(const float* __restrict__ b1) {
    extern __shared__ char sm[];
    const uint32_t sA = smem_u32(sm);
    const uint32_t sB = sA + STAGES * STAGE_SZ;
    const int t = threadIdx.x;
    const int n0 = blockIdx.x * 128;
    const int m0 = blockIdx.y * 128;
    const __half* gA = g_ctxh + (size_t)m0 * 2048;
    const __half* gB = g_W1t + (size_t)n0 * 2048;

    const int lrow = t >> 3, lcu = t & 7;   // cp.async: row, 16B-col

    const int warp = t >> 5, lane = t & 31;
    const int wm = warp & 3, wn = warp >> 2;
    // ldmatrix lane address components
    const int a_row = (lane & 7) + ((lane >> 3) & 1) * 8;
    const int a_kb  = (lane >> 4) << 4;
    const uint32_t aBase = (uint32_t)(wm * 32 + a_row) * 128 + a_kb;
    const int b_row = (lane & 7) + ((lane >> 4) << 3);
    const int b_kb  = ((lane >> 3) & 1) << 4;
    const uint32_t bBase = (uint32_t)(wn * 64 + b_row) * 128 + b_kb;

    float d[2][8][4];
#pragma unroll
    for (int mf = 0; mf < 2; mf++)
#pragma unroll
        for (int nf = 0; nf < 8; nf++)
#pragma unroll
            for (int q = 0; q < 4; q++) d[mf][nf][q] = 0.0f;

    auto load_stage = [&](int c, int slot) {
        const int k0 = c * 64;
#pragma unroll
        for (int i = 0; i < 4; i++) {
            int row = lrow + 32 * i;
            uint32_t dst = sA + slot * STAGE_SZ + SW128(row * 128 + lcu * 16);
            CP16(dst, gA + (size_t)row * 2048 + k0 + lcu * 8);
        }
#pragma unroll
        for (int i = 0; i < 4; i++) {
            int row = lrow + 32 * i;
            uint32_t dst = sB + slot * STAGE_SZ + SW128(row * 128 + lcu * 16);
            CP16(dst, gB + (size_t)row * 2048 + k0 + lcu * 8);
        }
    };

#pragma unroll
    for (int s = 0; s < STAGES - 1; s++) { load_stage(s, s); CP_COMMIT(); }

    for (int c = 0; c < 32; c++) {
        CP_WAIT2();
        __syncthreads();
        if (c + STAGES - 1 < 32) load_stage(c + STAGES - 1, (c + STAGES - 1) & (STAGES - 1));
        CP_COMMIT();

        const uint32_t slotA = sA + (c & (STAGES - 1)) * STAGE_SZ;
        const uint32_t slotB = sB + (c & (STAGES - 1)) * STAGE_SZ;
#pragma unroll
        for (int s = 0; s < 4; s++) {
            uint32_t a[2][4], bb[4][4];
#pragma unroll
            for (int mf = 0; mf < 2; mf++)
                LDSM_X4(a[mf], slotA + SW128(aBase + mf * 2048 + s * 32));
#pragma unroll
            for (int nb = 0; nb < 4; nb++)
                LDSM_X4(bb[nb], slotB + SW128(bBase + nb * 2048 + s * 32));
#pragma unroll
            for (int mf = 0; mf < 2; mf++)
#pragma unroll
                for (int nf = 0; nf < 8; nf++) {
                    const int nb = nf >> 1, h = (nf & 1) * 2;
                    MMA16816(d[mf][nf], a[mf], bb[nb][h], bb[nb][h + 1]);
                }
        }
        __syncthreads();
    }
    CP_WAIT0();

    // Epilogue: bias + relu + fp16 store
    const int gid = lane >> 2, tc = (lane & 3) * 2;
#pragma unroll
    for (int nf = 0; nf < 8; nf++) {
        const int col = n0 + wn * 64 + nf * 8 + tc;
        float2 bv = __ldg((const float2*)(b1 + col));
#pragma unroll
        for (int mf = 0; mf < 2; mf++) {
            const int r0 = m0 + wm * 32 + mf * 16 + gid;
            float* dd = d[mf][nf];
            __half2 h0 = __floats2half2_rn(fmaxf(dd[0] + bv.x, 0.0f), fmaxf(dd[1] + bv.y, 0.0f));
            __half2 h1 = __floats2half2_rn(fmaxf(dd[2] + bv.x, 0.0f), fmaxf(dd[3] + bv.y, 0.0f));
            *(__half2*)(g_embh + (size_t)r0 * 512 + col) = h0;
            *(__half2*)(g_embh + (size_t)(r0 + 8) * 512 + col) = h1;
        }
    }
}

// ---------------- Kernel 4: GEMM2 logits = emb @ W2 + b2 ----------------
#define G2_SMEM 204800
__global__ void __launch_bounds__(256) gemm2_kernel(const float* __restrict__ W2,
                                                    const float* __restrict__ b2,
                                                    float* __restrict__ logits) {
    extern __shared__ float w2s[];
    int tid = threadIdx.x;
    for (int i = tid; i < 51200; i += 256) w2s[i] = W2[i];
    __syncthreads();
    int rid = tid >> 3, ks = tid & 7;
    size_t row = (size_t)blockIdx.x * 32 + rid;
    const __half* e = g_embh + row * 5120;
    unsigned long long acc[5] = {0, 0, 0, 0, 0};
    for (int i = 0; i < 640; i++) {
        int k = (i << 3) + ks;  // lane-interleaved k -> conflict-free LDS
        float ev = __half2float(__ldg(e + k));
        unsigned long long evv;
        asm("mov.b64 %0, {%1, %1};" : "=l"(evv) : "f"(ev));
        const unsigned long long* w = (const unsigned long long*)(w2s + k * 10);
#pragma unroll
        for (int j = 0; j < 5; j++) {
            unsigned long long wv = w[j];
            asm("fma.rn.f32x2 %0, %1, %2, %3;"
                : "=l"(acc[j]) : "l"(evv), "l"(wv), "l"(acc[j]));
        }
    }
    float a10[10];
#pragma unroll
    for (int j = 0; j < 5; j++) {
        a10[2 * j]     = __uint_as_float((unsigned)(acc[j] & 0xFFFFFFFFull));
        a10[2 * j + 1] = __uint_as_float((unsigned)(acc[j] >> 32));
    }
#pragma unroll
    for (int off = 4; off >= 1; off >>= 1) {
#pragma unroll
        for (int j = 0; j < 10; j++)
            a10[j] += __shfl_xor_sync(0xFFFFFFFFu, a10[j], off);
    }
    if (ks == 0) {
#pragma unroll
        for (int j = 0; j < 10; j++)
            logits[row * 10 + j] = a10[j] + __ldg(b2 + j);
    }
}

// ---------------- Kernel 5: gather best_* by one-hot label ----------------
__global__ void gather_kernel(const float* __restrict__ lane, const float* __restrict__ nghl,
                              const float* __restrict__ ngh, const int* __restrict__ label,
                              float* __restrict__ out) {
    int b = blockIdx.x, tid = threadIdx.x;
    __shared__ int sidx;
    if (tid < 10 && label[b * 10 + tid] == 1) sidx = tid;
    __syncthreads();
    size_t src = ((size_t)b * 10 + sidx) * 512;
    float4 v1 = ((const float4*)(lane + src))[tid];
    float4 v2 = ((const float4*)(nghl + src))[tid];
    float4 v3 = ((const float4*)(ngh + src))[tid];
    ((float4*)(out + 40960 + (size_t)b * 512))[tid] = v1;
    ((float4*)(out + 40960 + 2097152 + (size_t)b * 512))[tid] = v2;
    ((float4*)(out + 40960 + 4194304 + (size_t)b * 512))[tid] = v3;
}

// ---------------- launch ----------------
extern "C" void kernel_launch(void* const* d_in, const int* in_sizes, int n_in,
                              void* d_out, int out_size) {
    const float* agent = (const float*)d_in[0];
    const float* lane  = (const float*)d_in[1];
    const float* nghl  = (const float*)d_in[2];
    const float* ngh   = (const float*)d_in[3];
    const int*   label = (const int*)d_in[4];
    const float* W1    = (const float*)d_in[5];
    const float* b1    = (const float*)d_in[6];
    const float* W2    = (const float*)d_in[7];
    const float* b2    = (const float*)d_in[8];
    float* out = (float*)d_out;

    cudaFuncSetAttribute(gemm1_kernel, cudaFuncAttributeMaxDynamicSharedMemorySize, G1_SMEM);
    cudaFuncSetAttribute(gemm2_kernel, cudaFuncAttributeMaxDynamicSharedMemorySize, G2_SMEM);

    w1t_kernel<<<dim3(64, 16), dim3(32, 8)>>>(W1);
    ctx_prep_kernel<<<40960, 256>>>(agent, lane, nghl, ngh);
    gemm1_kernel<<<dim3(4, 320), 256, G1_SMEM>>>(b1);
    gemm2_kernel<<<128, 256, G2_SMEM>>>(W2, b2, out);
    gather_kernel<<<4096, 128>>>(lane, nghl, ngh, label, out);
}

// round 4
// speedup vs baseline: 1.2838x; 1.2838x over previous
#include <cuda_runtime.h>
#include <cuda_fp16.h>
#include <cstdint>
#include <cstddef>

// Problem: B=4096, P=10, LD=TD=512, DIN=2048, BP=40960
// out = [logits 4096x10][best_lane 4096x512][best_nghl 4096x512][best_ngh 4096x512]
// Toolchain compiles via compute_103 PTX -> NO sm_103a-only features.
// Use mma.sync.m16n8k16 + cp.async (compute_80 features).

__device__ __align__(16) __half g_W1t[512 * 2048];        // W1^T fp16 [n][k]
__device__ __align__(16) __half g_ctxh[40960u * 2048];    // concat ctx fp16 [row][k]
__device__ __align__(16) __half g_embh[40960u * 512];     // relu(ctx@W1+b1) fp16 (= [4096][5120])
__device__ __align__(16) __half g_W2h[16 * 5120];         // W2^T padded fp16 [n16][k5120]

#define SW128(o) ((o) ^ (((o) >> 3) & 0x70))

__device__ __forceinline__ uint32_t smem_u32(const void* p) {
    uint32_t a;
    asm("{ .reg .u64 t; cvta.to.shared.u64 t, %1; cvt.u32.u64 %0, t; }" : "=r"(a) : "l"(p));
    return a;
}
__device__ __forceinline__ uint32_t pack_h2(float a, float b) {
    __half2 h = __floats2half2_rn(a, b);
    return *reinterpret_cast<uint32_t*>(&h);
}

#define CP16(dst, src) \
    asm volatile("cp.async.cg.shared.global [%0], [%1], 16;" :: "r"(dst), "l"(src) : "memory")
#define CP_COMMIT() asm volatile("cp.async.commit_group;" ::: "memory")
#define CP_WAIT2()  asm volatile("cp.async.wait_group 2;" ::: "memory")
#define CP_WAIT0()  asm volatile("cp.async.wait_group 0;" ::: "memory")

#define LDSM_X4(r, addr)                                                          \
    asm volatile("ldmatrix.sync.aligned.m8n8.x4.shared.b16 {%0,%1,%2,%3}, [%4];"  \
        : "=r"((r)[0]), "=r"((r)[1]), "=r"((r)[2]), "=r"((r)[3]) : "r"(addr))

#define MMA16816(d, a, b0, b1)                                                    \
    asm volatile("mma.sync.aligned.m16n8k16.row.col.f32.f16.f16.f32 "             \
        "{%0,%1,%2,%3}, {%4,%5,%6,%7}, {%8,%9}, {%0,%1,%2,%3};"                    \
        : "+f"((d)[0]), "+f"((d)[1]), "+f"((d)[2]), "+f"((d)[3])                   \
        : "r"((a)[0]), "r"((a)[1]), "r"((a)[2]), "r"((a)[3]), "r"(b0), "r"(b1))

// ---------------- Kernel 1: W1[2048,512] f32 -> W1t[512][2048] f16 ----------------
__global__ void w1t_kernel(const float* __restrict__ W1) {
    __shared__ float t[32][33];
    int kk = blockIdx.x * 32, nn = blockIdx.y * 32;
    int tx = threadIdx.x, ty = threadIdx.y;  // 32 x 8
#pragma unroll
    for (int q = 0; q < 4; q++)
        t[ty + 8 * q][tx] = W1[(size_t)(kk + ty + 8 * q) * 512 + nn + tx];
    __syncthreads();
#pragma unroll
    for (int q = 0; q < 4; q++)
        g_W1t[(size_t)(nn + ty + 8 * q) * 2048 + kk + tx] = __float2half(t[tx][ty + 8 * q]);
}

// ---------------- Kernel 2: fused concat + f32->f16 ----------------
__global__ void __launch_bounds__(256) ctx_prep_kernel(
    const float* __restrict__ agent, const float* __restrict__ lane,
    const float* __restrict__ nghl,  const float* __restrict__ ngh)
{
    int row = blockIdx.x;
    int t = threadIdx.x;
    int b = row / 10;
    int seg = t >> 6;
    int off = (t & 63) * 8;
    const float* src;
    if (seg == 0)      src = agent + (size_t)b * 512 + off;
    else if (seg == 1) src = lane + (size_t)row * 512 + off;
    else if (seg == 2) src = nghl + (size_t)row * 512 + off;
    else               src = ngh  + (size_t)row * 512 + off;
    float4 v0 = __ldg((const float4*)src);
    float4 v1 = __ldg((const float4*)src + 1);
    uint4 o;
    o.x = pack_h2(v0.x, v0.y); o.y = pack_h2(v0.z, v0.w);
    o.z = pack_h2(v1.x, v1.y); o.w = pack_h2(v1.z, v1.w);
    *(uint4*)(g_ctxh + (size_t)row * 2048 + t * 8) = o;
}

// ---------------- Kernel 3: W2[5120,10] f32 -> W2h[16][5120] f16 (zero-padded) -----
__global__ void __launch_bounds__(256) w2h_kernel(const float* __restrict__ W2) {
    int idx = blockIdx.x * 256 + threadIdx.x;      // 81920
    int n = idx / 5120, k = idx % 5120;
    g_W2h[idx] = __float2half(n < 10 ? W2[(size_t)k * 10 + n] : 0.0f);
}

// ---------------- Kernel 4: logits init = b2 ----------------
__global__ void __launch_bounds__(256) logits_init_kernel(const float* __restrict__ b2,
                                                          float* __restrict__ logits) {
    int idx = blockIdx.x * 256 + threadIdx.x;      // 40960
    logits[idx] = __ldg(b2 + idx % 10);
}

// ---------------- Kernel 5: GEMM1 emb = relu(ctx @ W1 + b1) ----------------
// CTA tile 128m x 256n, 8 warps (2m x 4n), warp tile 64x64, K-chunk 64, 4-stage cp.async.
#define STAGES    4
#define A_STAGE   16384                    // 128 rows x 128B
#define B_STAGE   32768                    // 256 rows x 128B
#define G1_SMEM   (STAGES * (A_STAGE + B_STAGE))   // 196608

__global__ void __launch_bounds__(256, 1) gemm1_kernel(const float* __restrict__ b1) {
    extern __shared__ char sm[];
    const uint32_t sA = smem_u32(sm);
    const uint32_t sB = sA + STAGES * A_STAGE;
    const int t = threadIdx.x;
    const int n0 = blockIdx.x * 256;
    const int m0 = blockIdx.y * 128;
    const __half* gA = g_ctxh + (size_t)m0 * 2048;
    const __half* gB = g_W1t + (size_t)n0 * 2048;

    const int lrow = t >> 3, lcu = t & 7;

    const int warp = t >> 5, lane = t & 31;
    const int wm = warp & 1, wn = warp >> 1;
    const int a_row = (lane & 7) + ((lane >> 3) & 1) * 8;
    const int a_kb  = (lane >> 4) << 4;
    const uint32_t aBase = (uint32_t)(wm * 64 + a_row) * 128 + a_kb;
    const int b_row = (lane & 7) + ((lane >> 4) << 3);
    const int b_kb  = ((lane >> 3) & 1) << 4;
    const uint32_t bBase = (uint32_t)(wn * 64 + b_row) * 128 + b_kb;

    float d[4][8][4];
#pragma unroll
    for (int mf = 0; mf < 4; mf++)
#pragma unroll
        for (int nf = 0; nf < 8; nf++)
#pragma unroll
            for (int q = 0; q < 4; q++) d[mf][nf][q] = 0.0f;

    auto load_stage = [&](int c, int slot) {
        const int k0 = c * 64;
#pragma unroll
        for (int i = 0; i < 4; i++) {
            int row = lrow + 32 * i;
            uint32_t dst = sA + slot * A_STAGE + SW128(row * 128 + lcu * 16);
            CP16(dst, gA + (size_t)row * 2048 + k0 + lcu * 8);
        }
#pragma unroll
        for (int i = 0; i < 8; i++) {
            int row = lrow + 32 * i;
            uint32_t dst = sB + slot * B_STAGE + SW128(row * 128 + lcu * 16);
            CP16(dst, gB + (size_t)row * 2048 + k0 + lcu * 8);
        }
    };

#pragma unroll
    for (int s = 0; s < STAGES - 1; s++) { load_stage(s, s); CP_COMMIT(); }

    for (int c = 0; c < 32; c++) {
        CP_WAIT2();
        __syncthreads();
        if (c + STAGES - 1 < 32) load_stage(c + STAGES - 1, (c + STAGES - 1) & (STAGES - 1));
        CP_COMMIT();

        const uint32_t slotA = sA + (c & (STAGES - 1)) * A_STAGE;
        const uint32_t slotB = sB + (c & (STAGES - 1)) * B_STAGE;
#pragma unroll
        for (int s = 0; s < 4; s++) {
            uint32_t a[4][4], bb[4][4];
#pragma unroll
            for (int mf = 0; mf < 4; mf++)
                LDSM_X4(a[mf], slotA + SW128(aBase + mf * 2048 + s * 32));
#pragma unroll
            for (int nb = 0; nb < 4; nb++)
                LDSM_X4(bb[nb], slotB + SW128(bBase + nb * 2048 + s * 32));
#pragma unroll
            for (int mf = 0; mf < 4; mf++)
#pragma unroll
                for (int nf = 0; nf < 8; nf++) {
                    const int nb = nf >> 1, h = (nf & 1) * 2;
                    MMA16816(d[mf][nf], a[mf], bb[nb][h], bb[nb][h + 1]);
                }
        }
        __syncthreads();
    }
    CP_WAIT0();

    const int gid = lane >> 2, tc = (lane & 3) * 2;
#pragma unroll
    for (int nf = 0; nf < 8; nf++) {
        const int col = n0 + wn * 64 + nf * 8 + tc;
        float2 bv = __ldg((const float2*)(b1 + col));
#pragma unroll
        for (int mf = 0; mf < 4; mf++) {
            const int r0 = m0 + wm * 64 + mf * 16 + gid;
            float* dd = d[mf][nf];
            __half2 h0 = __floats2half2_rn(fmaxf(dd[0] + bv.x, 0.0f), fmaxf(dd[1] + bv.y, 0.0f));
            __half2 h1 = __floats2half2_rn(fmaxf(dd[2] + bv.x, 0.0f), fmaxf(dd[3] + bv.y, 0.0f));
            *(__half2*)(g_embh + (size_t)r0 * 512 + col) = h0;
            *(__half2*)(g_embh + (size_t)(r0 + 8) * 512 + col) = h1;
        }
    }
}

// ---------------- Kernel 6: GEMM2 logits += emb[4096,5120] @ W2h^T via mma ----------
// CTA: 128 rows x n16, 8 warps (m16 each), K-split 4 (1280 each = 20 chunks of 64).
#define G2_STAGES  4
#define G2_A_STAGE 16384                   // 128 x 128B
#define G2_B_STAGE 2048                    // 16 x 128B
#define G2_SMEM    (G2_STAGES * (G2_A_STAGE + G2_B_STAGE))  // 73728

__global__ void __launch_bounds__(256, 1) gemm2_kernel(float* __restrict__ logits) {
    extern __shared__ char sm[];
    const uint32_t sA = smem_u32(sm);
    const uint32_t sB = sA + G2_STAGES * G2_A_STAGE;
    const int t = threadIdx.x;
    const int m0 = blockIdx.x * 128;       // 32 m-blocks
    const int kbase = blockIdx.y * 1280;   // 4 k-splits
    const __half* gA = g_embh + (size_t)m0 * 5120 + kbase;   // emb flat [4096][5120]
    const __half* gB = g_W2h + kbase;

    const int lrow = t >> 3, lcu = t & 7;
    const int warp = t >> 5, lane = t & 31;
    const int a_row = (lane & 7) + ((lane >> 3) & 1) * 8;
    const int a_kb  = (lane >> 4) << 4;
    const uint32_t aBase = (uint32_t)(warp * 16 + a_row) * 128 + a_kb;
    const int b_row = (lane & 7) + ((lane >> 4) << 3);
    const int b_kb  = ((lane >> 3) & 1) << 4;
    const uint32_t bBase = (uint32_t)b_row * 128 + b_kb;

    float d[2][4];
#pragma unroll
    for (int nf = 0; nf < 2; nf++)
#pragma unroll
        for (int q = 0; q < 4; q++) d[nf][q] = 0.0f;

    auto load_stage = [&](int c, int slot) {
        const int k0 = c * 64;
#pragma unroll
        for (int i = 0; i < 4; i++) {
            int row = lrow + 32 * i;
            uint32_t dst = sA + slot * G2_A_STAGE + SW128(row * 128 + lcu * 16);
            CP16(dst, gA + (size_t)row * 5120 + k0 + lcu * 8);
        }
        if (t < 128) {
            int row = t >> 3;
            uint32_t dst = sB + slot * G2_B_STAGE + SW128(row * 128 + lcu * 16);
            CP16(dst, gB + (size_t)row * 5120 + k0 + lcu * 8);
        }
    };

#pragma unroll
    for (int s = 0; s < G2_STAGES - 1; s++) { load_stage(s, s); CP_COMMIT(); }

    for (int c = 0; c < 20; c++) {
        CP_WAIT2();
        __syncthreads();
        if (c + G2_STAGES - 1 < 20) load_stage(c + G2_STAGES - 1, (c + G2_STAGES - 1) & 3);
        CP_COMMIT();

        const uint32_t slotA = sA + (c & 3) * G2_A_STAGE;
        const uint32_t slotB = sB + (c & 3) * G2_B_STAGE;
#pragma unroll
        for (int s = 0; s < 4; s++) {
            uint32_t a[4], bb[4];
            LDSM_X4(a, slotA + SW128(aBase + s * 32));
            LDSM_X4(bb, slotB + SW128(bBase + s * 32));
            MMA16816(d[0], a, bb[0], bb[1]);
            MMA16816(d[1], a, bb[2], bb[3]);
        }
        __syncthreads();
    }
    CP_WAIT0();

    const int gid = lane >> 2, tc = (lane & 3) * 2;
#pragma unroll
    for (int nf = 0; nf < 2; nf++)
#pragma unroll
        for (int q = 0; q < 4; q++) {
            int col = nf * 8 + tc + (q & 1);
            int row = m0 + warp * 16 + gid + (q >> 1) * 8;
            if (col < 10) atomicAdd(&logits[(size_t)row * 10 + col], d[nf][q]);
        }
}

// ---------------- Kernel 7: gather best_* by one-hot label ----------------
__global__ void gather_kernel(const float* __restrict__ lane, const float* __restrict__ nghl,
                              const float* __restrict__ ngh, const int* __restrict__ label,
                              float* __restrict__ out) {
    int b = blockIdx.x, tid = threadIdx.x;
    __shared__ int sidx;
    if (tid < 10 && label[b * 10 + tid] == 1) sidx = tid;
    __syncthreads();
    size_t src = ((size_t)b * 10 + sidx) * 512;
    float4 v1 = ((const float4*)(lane + src))[tid];
    float4 v2 = ((const float4*)(nghl + src))[tid];
    float4 v3 = ((const float4*)(ngh + src))[tid];
    ((float4*)(out + 40960 + (size_t)b * 512))[tid] = v1;
    ((float4*)(out + 40960 + 2097152 + (size_t)b * 512))[tid] = v2;
    ((float4*)(out + 40960 + 4194304 + (size_t)b * 512))[tid] = v3;
}

// ---------------- launch ----------------
extern "C" void kernel_launch(void* const* d_in, const int* in_sizes, int n_in,
                              void* d_out, int out_size) {
    const float* agent = (const float*)d_in[0];
    const float* lane  = (const float*)d_in[1];
    const float* nghl  = (const float*)d_in[2];
    const float* ngh   = (const float*)d_in[3];
    const int*   label = (const int*)d_in[4];
    const float* W1    = (const float*)d_in[5];
    const float* b1    = (const float*)d_in[6];
    const float* W2    = (const float*)d_in[7];
    const float* b2    = (const float*)d_in[8];
    float* out = (float*)d_out;

    cudaFuncSetAttribute(gemm1_kernel, cudaFuncAttributeMaxDynamicSharedMemorySize, G1_SMEM);
    cudaFuncSetAttribute(gemm2_kernel, cudaFuncAttributeMaxDynamicSharedMemorySize, G2_SMEM);

    w1t_kernel<<<dim3(64, 16), dim3(32, 8)>>>(W1);
    ctx_prep_kernel<<<40960, 256>>>(agent, lane, nghl, ngh);
    w2h_kernel<<<320, 256>>>(W2);
    logits_init_kernel<<<160, 256>>>(b2, out);
    gemm1_kernel<<<dim3(2, 320), 256, G1_SMEM>>>(b1);
    gemm2_kernel<<<dim3(32, 4), 256, G2_SMEM>>>(out);
    gather_kernel<<<4096, 128>>>(lane, nghl, ngh, label, out);
}